// round 1
// baseline (speedup 1.0000x reference)
#include <cuda_runtime.h>
#include <stdint.h>

// Problem dims
#define T_STEPS 100
#define BATCH   512
#define NI      784
#define NH      1024
#define NO      10
#define M_TOT   (T_STEPS * BATCH)   // 51200

// Scratch (static __device__ arrays: allocation-free per harness rules)
__device__ float          g_cur1[(size_t)M_TOT * NH];   // ~210 MB
__device__ unsigned char  g_spk1[(size_t)M_TOT * NH];   // ~52 MB
__device__ float          g_cur2[(size_t)M_TOT * NO];   // ~2 MB

// ---------------------------------------------------------------------------
// Kernel A: cur1[m,n] = sum_k X[m,k]*W1[n,k] + b1[n]
// Classic 128x128x16 fp32 SGEMM, 256 threads, 8x8 microtile (split 4+4),
// register-prefetched global loads.
// ---------------------------------------------------------------------------
__global__ __launch_bounds__(256, 2) void k_gemm1(const float* __restrict__ X,
                                                  const float* __restrict__ W1,
                                                  const float* __restrict__ bias) {
    __shared__ float As[16][128];
    __shared__ float Bs[16][128];
    const int K = NI;       // 784 = 49 * 16
    const int N = NH;       // 1024

    int tid = threadIdx.x;
    int bn  = blockIdx.x;   // 0..7
    int bm  = blockIdx.y;   // 0..399

    int lrow = tid >> 1;          // 0..127
    int lcol = (tid & 1) << 3;    // 0 or 8

    const float* aptr = X  + (size_t)(bm * 128 + lrow) * K + lcol;
    const float* bptr = W1 + (size_t)(bn * 128 + lrow) * K + lcol;

    int ty = tid >> 4;   // 0..15
    int tx = tid & 15;   // 0..15

    float acc[8][8];
#pragma unroll
    for (int i = 0; i < 8; i++)
#pragma unroll
        for (int j = 0; j < 8; j++) acc[i][j] = 0.0f;

    // prefetch first tile
    float4 a0 = *(const float4*)(aptr);
    float4 a1 = *(const float4*)(aptr + 4);
    float4 b0 = *(const float4*)(bptr);
    float4 b1 = *(const float4*)(bptr + 4);

    for (int k0 = 0; k0 < K; k0 += 16) {
        __syncthreads();
        As[lcol + 0][lrow] = a0.x; As[lcol + 1][lrow] = a0.y;
        As[lcol + 2][lrow] = a0.z; As[lcol + 3][lrow] = a0.w;
        As[lcol + 4][lrow] = a1.x; As[lcol + 5][lrow] = a1.y;
        As[lcol + 6][lrow] = a1.z; As[lcol + 7][lrow] = a1.w;
        Bs[lcol + 0][lrow] = b0.x; Bs[lcol + 1][lrow] = b0.y;
        Bs[lcol + 2][lrow] = b0.z; Bs[lcol + 3][lrow] = b0.w;
        Bs[lcol + 4][lrow] = b1.x; Bs[lcol + 5][lrow] = b1.y;
        Bs[lcol + 6][lrow] = b1.z; Bs[lcol + 7][lrow] = b1.w;
        __syncthreads();

        if (k0 + 16 < K) {   // prefetch next tile (overlaps with FFMAs below)
            a0 = *(const float4*)(aptr + k0 + 16);
            a1 = *(const float4*)(aptr + k0 + 20);
            b0 = *(const float4*)(bptr + k0 + 16);
            b1 = *(const float4*)(bptr + k0 + 20);
        }

#pragma unroll
        for (int kk = 0; kk < 16; kk++) {
            float4 aA = *(const float4*)&As[kk][ty * 4];
            float4 aB = *(const float4*)&As[kk][ty * 4 + 64];
            float4 bA = *(const float4*)&Bs[kk][tx * 4];
            float4 bB = *(const float4*)&Bs[kk][tx * 4 + 64];
            float av[8] = {aA.x, aA.y, aA.z, aA.w, aB.x, aB.y, aB.z, aB.w};
            float bv[8] = {bA.x, bA.y, bA.z, bA.w, bB.x, bB.y, bB.z, bB.w};
#pragma unroll
            for (int i = 0; i < 8; i++)
#pragma unroll
                for (int j = 0; j < 8; j++)
                    acc[i][j] += av[i] * bv[j];
        }
    }

    // Epilogue: rows = bm*128 + {ty*4+i, ty*4+64+i}, cols = bn*128 + {tx*4+j, tx*4+64+j}
    int crow0 = bm * 128 + ty * 4;
    int ccol0 = bn * 128 + tx * 4;
    float4 bs0 = *(const float4*)(bias + ccol0);
    float4 bs1 = *(const float4*)(bias + ccol0 + 64);

#pragma unroll
    for (int i = 0; i < 4; i++) {
        float* c0 = g_cur1 + (size_t)(crow0 + i) * N + ccol0;
        float4 v;
        v.x = acc[i][0] + bs0.x; v.y = acc[i][1] + bs0.y;
        v.z = acc[i][2] + bs0.z; v.w = acc[i][3] + bs0.w;
        *(float4*)(c0) = v;
        v.x = acc[i][4] + bs1.x; v.y = acc[i][5] + bs1.y;
        v.z = acc[i][6] + bs1.z; v.w = acc[i][7] + bs1.w;
        *(float4*)(c0 + 64) = v;

        float* c1 = g_cur1 + (size_t)(crow0 + 64 + i) * N + ccol0;
        v.x = acc[4 + i][0] + bs0.x; v.y = acc[4 + i][1] + bs0.y;
        v.z = acc[4 + i][2] + bs0.z; v.w = acc[4 + i][3] + bs0.w;
        *(float4*)(c1) = v;
        v.x = acc[4 + i][4] + bs1.x; v.y = acc[4 + i][5] + bs1.y;
        v.z = acc[4 + i][6] + bs1.z; v.w = acc[4 + i][7] + bs1.w;
        *(float4*)(c1 + 64) = v;
    }
}

// ---------------------------------------------------------------------------
// Kernel B: layer-1 leaky scan per (b,n). 524288 independent threads.
// ---------------------------------------------------------------------------
__global__ __launch_bounds__(256) void k_scan1() {
    int idx = blockIdx.x * blockDim.x + threadIdx.x;   // 0 .. B*NH-1
    const size_t stride = (size_t)BATCH * NH;
    float m = 0.0f;
#pragma unroll 4
    for (int t = 0; t < T_STEPS; t++) {
        float c = g_cur1[(size_t)t * stride + idx];
        float reset = (m > 1.0f) ? 1.0f : 0.0f;
        m = 0.9f * m + c - reset;
        g_spk1[(size_t)t * stride + idx] = (m > 1.0f) ? (unsigned char)1 : (unsigned char)0;
    }
}

// ---------------------------------------------------------------------------
// Kernel C: cur2[tb,j] = sum_n spk1[tb,n]*W2[j,n] + b2[j]
// Block = 128 tb-rows; W2 staged in smem (40 KB); spikes tiled 128x32 bytes.
// ---------------------------------------------------------------------------
__global__ __launch_bounds__(128) void k_gemm2(const float* __restrict__ W2,
                                               const float* __restrict__ b2) {
    __shared__ float         w2s[NO * NH];        // 40960 B
    __shared__ unsigned char sp[128 * 36];        // 128 rows, 32B + 4B pad

    int tid = threadIdx.x;
    int tb0 = blockIdx.x * 128;

    // load W2 into shared (coalesced float4)
    const float4* w2g = (const float4*)W2;
    float4* w2s4 = (float4*)w2s;
#pragma unroll
    for (int i = tid; i < (NO * NH) / 4; i += 128) w2s4[i] = w2g[i];

    float acc[NO];
#pragma unroll
    for (int j = 0; j < NO; j++) acc[j] = 0.0f;

    for (int kc = 0; kc < NH / 32; kc++) {   // 32 chunks of 32 n
        __syncthreads();
        // load 128 rows x 32 bytes of spikes -> smem (padded stride 36)
#pragma unroll
        for (int i = 0; i < 8; i++) {
            int lin = i * 128 + tid;       // 0..1023 uint32 slots
            int r = lin >> 3;              // 0..127
            int c = lin & 7;               // 0..7
            uint32_t v = *(const uint32_t*)(g_spk1 + (size_t)(tb0 + r) * NH + kc * 32 + c * 4);
            *(uint32_t*)(sp + r * 36 + c * 4) = v;
        }
        __syncthreads();

        const uint32_t* myrow = (const uint32_t*)(sp + tid * 36);
#pragma unroll
        for (int g = 0; g < 8; g++) {
            uint32_t v = myrow[g];
            float s0 = (float)(v & 1u);
            float s1 = (float)((v >> 8) & 1u);
            float s2 = (float)((v >> 16) & 1u);
            float s3 = (float)((v >> 24) & 1u);
            int fidx = kc * 8 + g;   // float4 index within a W2 row
#pragma unroll
            for (int j = 0; j < NO; j++) {
                float4 w = ((const float4*)(w2s + j * NH))[fidx];
                acc[j] += s0 * w.x;
                acc[j] += s1 * w.y;
                acc[j] += s2 * w.z;
                acc[j] += s3 * w.w;
            }
        }
    }

#pragma unroll
    for (int j = 0; j < NO; j++)
        g_cur2[(size_t)(tb0 + tid) * NO + j] = acc[j] + __ldg(&b2[j]);
}

// ---------------------------------------------------------------------------
// Kernel D: layer-2 leaky scan per (b,o); writes spk2_rec then final mem2.
// cur2 staged through smem in T-chunks of 25 to hide DRAM latency.
// ---------------------------------------------------------------------------
__global__ __launch_bounds__(256) void k_scan2(float* __restrict__ out) {
    __shared__ float sc[25][256];
    int idx = blockIdx.x * 256 + threadIdx.x;   // 0 .. B*NO-1 (5120)
    const int stride = BATCH * NO;              // 5120
    float m = 0.0f;
    for (int tc = 0; tc < 4; tc++) {
        __syncthreads();
#pragma unroll
        for (int j = 0; j < 25; j++)
            sc[j][threadIdx.x] = g_cur2[(size_t)(tc * 25 + j) * stride + idx];
        __syncthreads();
#pragma unroll
        for (int j = 0; j < 25; j++) {
            int t = tc * 25 + j;
            float c = sc[j][threadIdx.x];
            float reset = (m > 1.0f) ? 1.0f : 0.0f;
            m = 0.9f * m + c - reset;
            out[(size_t)t * stride + idx] = (m > 1.0f) ? 1.0f : 0.0f;
        }
    }
    out[(size_t)T_STEPS * stride + idx] = m;   // final mem2
}

// ---------------------------------------------------------------------------
extern "C" void kernel_launch(void* const* d_in, const int* in_sizes, int n_in,
                              void* d_out, int out_size) {
    const float* x  = (const float*)d_in[0];   // [T,B,NI]
    const float* W1 = (const float*)d_in[1];   // [NH,NI]
    const float* b1 = (const float*)d_in[2];   // [NH]
    const float* W2 = (const float*)d_in[3];   // [NO,NH]
    const float* b2 = (const float*)d_in[4];   // [NO]
    float* out = (float*)d_out;                // [T*B*NO + B*NO]

    // A: big GEMM cur1 = x @ W1^T + b1
    dim3 gridA(NH / 128, M_TOT / 128);         // (8, 400)
    k_gemm1<<<gridA, 256>>>(x, W1, b1);

    // B: layer-1 scan -> spikes
    k_scan1<<<(BATCH * NH) / 256, 256>>>();

    // C: cur2 = spk1 @ W2^T + b2
    k_gemm2<<<M_TOT / 128, 128>>>(W2, b2);

    // D: layer-2 scan -> output spikes + final mem2
    k_scan2<<<(BATCH * NO) / 256, 256>>>(out);
}